// round 7
// baseline (speedup 1.0000x reference)
#include <cuda_runtime.h>

#define BB 128
#define NN 4096
#define SD 448
#define NCH 4

__device__ float g_slots[BB * SD];
__device__ float g_qk[BB * SD];
__device__ float g_part[BB * NCH * SD];
__device__ float g_pden[BB * NCH * 7];
__device__ float g_M[64 * 64];

typedef unsigned long long ull;

__device__ __forceinline__ void fma2(ull& c, ull a, ull b) {
    asm("fma.rn.f32x2 %0, %1, %2, %0;" : "+l"(c) : "l"(a), "l"(b));
}
__device__ __forceinline__ ull pk2(float x, float y) {
    ull r; asm("mov.b64 %0, {%1, %2};" : "=l"(r) : "f"(x), "f"(y)); return r;
}
__device__ __forceinline__ float2 up2(ull v) {
    float2 r; asm("mov.b64 {%0, %1}, %2;" : "=f"(r.x), "=f"(r.y) : "l"(v)); return r;
}
__device__ __forceinline__ float ex2a(float x) {
    float y; asm("ex2.approx.f32 %0, %1;" : "=f"(y) : "f"(x)); return y;
}
__device__ __forceinline__ float rcpa(float x) {
    float y; asm("rcp.approx.f32 %0, %1;" : "=f"(y) : "f"(x)); return y;
}
__device__ __forceinline__ float sigf(float x) { return 1.0f / (1.0f + __expf(-x)); }

// ================= kprep: M = C * Wq^T @ Wk (once) =================
__global__ void kprep(const float* __restrict__ Wq, const float* __restrict__ Wk) {
    int e = blockIdx.x, d = threadIdx.x;
    float acc = 0.f;
#pragma unroll 16
    for (int j = 0; j < 64; j++)
        acc = fmaf(Wq[j * 64 + e], Wk[j * 64 + d], acc);
    g_M[e * 64 + d] = acc * 0.18033688011112042f;  // D^-0.5 * log2(e)
}

// ====== kinitq: slots init + LN(slots) + qk = sn @ M ======
__global__ __launch_bounds__(448) void kinitq(
    const float* __restrict__ nbg, const float* __restrict__ nfg,
    const float* __restrict__ bmu, const float* __restrict__ bls,
    const float* __restrict__ fmu, const float* __restrict__ fls,
    const float* __restrict__ lg, const float* __restrict__ lb) {
    __shared__ __align__(16) float sn[7][64];
    __shared__ float s_red[14][2];
    int b = blockIdx.x, t = threadIdx.x, s = t >> 6, d = t & 63, w = t >> 5;
    float val;
    if (s == 0) val = bmu[d] + expf(bls[d]) * nbg[b * 64 + d];
    else        val = fmu[d] + expf(fls[d]) * nfg[(b * 6 + (s - 1)) * 64 + d];
    g_slots[b * SD + t] = val;

    float s1 = val, s2 = val * val;
#pragma unroll
    for (int off = 16; off; off >>= 1) {
        s1 += __shfl_xor_sync(0xffffffffu, s1, off);
        s2 += __shfl_xor_sync(0xffffffffu, s2, off);
    }
    if ((t & 31) == 0) { s_red[w][0] = s1; s_red[w][1] = s2; }
    __syncthreads();
    float tot  = s_red[2 * s][0] + s_red[2 * s + 1][0];
    float tot2 = s_red[2 * s][1] + s_red[2 * s + 1][1];
    float mu = tot * (1.0f / 64.0f);
    float rs = rsqrtf(tot2 * (1.0f / 64.0f) - mu * mu + 1e-5f);
    sn[s][d] = fmaf((val - mu) * rs, lg[d], lb[d]);
    __syncthreads();

    float acc = 0.f;
    const float4* sn4 = (const float4*)sn[s];
#pragma unroll
    for (int i = 0; i < 16; i++) {
        float4 x = sn4[i];
        float m0 = g_M[(4 * i + 0) * 64 + d], m1 = g_M[(4 * i + 1) * 64 + d];
        float m2 = g_M[(4 * i + 2) * 64 + d], m3 = g_M[(4 * i + 3) * 64 + d];
        acc = fmaf(x.x, m0, acc); acc = fmaf(x.y, m1, acc);
        acc = fmaf(x.z, m2, acc); acc = fmaf(x.w, m3, acc);
    }
    g_qk[b * SD + t] = acc;
}

// ===== kattn: fused LN(inputs) -> logits -> softmax(+eps) -> U/den partials =====
__global__ __launch_bounds__(256, 2) void kattn(const float* __restrict__ x,
                                                const float* __restrict__ lg,
                                                const float* __restrict__ lb) {
    __shared__ __align__(16) float s_qk[7][64];
    __shared__ float s_u[8][7][64];
    __shared__ float s_d[8][7];
    int b = blockIdx.y, chunk = blockIdx.x;
    int tid = threadIdx.x, warp = tid >> 5, lane = tid & 31;
    int grp = lane >> 3, sub = lane & 7, d0 = sub << 3;

    for (int i = tid; i < SD; i += 256)
        ((float*)s_qk)[i] = g_qk[b * SD + i];

    float lng[8], lnb[8];
#pragma unroll
    for (int j = 0; j < 8; j++) { lng[j] = lg[d0 + j]; lnb[j] = lb[d0 + j]; }

    ull U[7][4];
    float den[7];
#pragma unroll
    for (int s = 0; s < 7; s++) {
        den[s] = 0.f;
#pragma unroll
        for (int j = 0; j < 4; j++) U[s][j] = 0ull;
    }
    __syncthreads();

    const int ROWS = NN / NCH;          // 1024 rows per block
    const int STEPS = ROWS / 32;        // 32 steps per group
    const float* xp = x + ((size_t)b * NN + chunk * ROWS + warp * 4 + grp) * 64 + d0;
    float4 cx0 = *(const float4*)xp;
    float4 cx1 = *(const float4*)(xp + 4);

#pragma unroll 4
    for (int step = 0; step < STEPS; step++) {
        float4 nx0 = cx0, nx1 = cx1;
        if (step < STEPS - 1) {
            xp += 32 * 64;
            nx0 = *(const float4*)xp;
            nx1 = *(const float4*)(xp + 4);
        }
        float xf[8] = {cx0.x, cx0.y, cx0.z, cx0.w, cx1.x, cx1.y, cx1.z, cx1.w};
        float s1 = 0.f, s2 = 0.f;
#pragma unroll
        for (int j = 0; j < 8; j++) { s1 += xf[j]; s2 = fmaf(xf[j], xf[j], s2); }
#pragma unroll
        for (int off = 1; off <= 4; off <<= 1) {
            s1 += __shfl_xor_sync(0xffffffffu, s1, off);
            s2 += __shfl_xor_sync(0xffffffffu, s2, off);
        }
        float mu = s1 * (1.0f / 64.0f);
        float rs = rsqrtf(s2 * (1.0f / 64.0f) - mu * mu + 1e-5f);
        ull p[4];
#pragma unroll
        for (int j = 0; j < 4; j++) {
            float a0 = fmaf((xf[2 * j]     - mu) * rs, lng[2 * j],     lnb[2 * j]);
            float a1 = fmaf((xf[2 * j + 1] - mu) * rs, lng[2 * j + 1], lnb[2 * j + 1]);
            p[j] = pk2(a0, a1);
        }
        float l[7];
#pragma unroll
        for (int s = 0; s < 7; s++) {
            const ull* qrow = (const ull*)&s_qk[s][d0];
            ull acc = 0ull;
            fma2(acc, p[0], qrow[0]); fma2(acc, p[1], qrow[1]);
            fma2(acc, p[2], qrow[2]); fma2(acc, p[3], qrow[3]);
            float2 pf = up2(acc);
            l[s] = pf.x + pf.y;
        }
#pragma unroll
        for (int off = 1; off <= 4; off <<= 1)
#pragma unroll
            for (int s = 0; s < 7; s++)
                l[s] += __shfl_xor_sync(0xffffffffu, l[s], off);
        // softmax without max-subtraction (|l| is small; exactly invariant math)
        float e[7], ws = 0.f;
#pragma unroll
        for (int s = 0; s < 7; s++) { e[s] = ex2a(l[s]); ws += e[s]; }
        float rinv = rcpa(ws);
#pragma unroll
        for (int s = 0; s < 7; s++) {
            float wv = fmaf(e[s], rinv, 1e-8f);
            den[s] += wv;
            ull wp = pk2(wv, wv);
            fma2(U[s][0], wp, p[0]); fma2(U[s][1], wp, p[1]);
            fma2(U[s][2], wp, p[2]); fma2(U[s][3], wp, p[3]);
        }
        cx0 = nx0; cx1 = nx1;
    }

    float u[7][8];
#pragma unroll
    for (int s = 0; s < 7; s++)
#pragma unroll
        for (int j = 0; j < 4; j++) {
            float2 t2 = up2(U[s][j]);
            u[s][2 * j] = t2.x; u[s][2 * j + 1] = t2.y;
        }
#pragma unroll
    for (int off = 8; off <= 16; off <<= 1) {
#pragma unroll
        for (int s = 0; s < 7; s++) {
#pragma unroll
            for (int j = 0; j < 8; j++)
                u[s][j] += __shfl_xor_sync(0xffffffffu, u[s][j], off);
            den[s] += __shfl_xor_sync(0xffffffffu, den[s], off);
        }
    }
    if (lane < 8) {
#pragma unroll
        for (int s = 0; s < 7; s++)
#pragma unroll
            for (int j = 0; j < 8; j++)
                s_u[warp][s][lane * 8 + j] = u[s][j];
    }
    if (lane == 0)
#pragma unroll
        for (int s = 0; s < 7; s++) s_d[warp][s] = den[s];
    __syncthreads();

    float* outp = g_part + (size_t)(b * NCH + chunk) * SD;
    for (int idx = tid; idx < SD; idx += 256) {
        int s = idx >> 6, d = idx & 63;
        float a = 0.f;
#pragma unroll
        for (int w8 = 0; w8 < 8; w8++) a += s_u[w8][s][d];
        outp[idx] = a;
    }
    if (tid < 7) {
        float a = 0.f;
#pragma unroll
        for (int w8 = 0; w8 < 8; w8++) a += s_d[w8][tid];
        g_pden[(b * NCH + chunk) * 7 + tid] = a;
    }
}

// ===== kupd: partial-reduce -> Wv -> GRU -> LN -> MLP -> (next qk) =====
// block = 128: warps 0-1 (g=0) own slots 0..3; warps 2-3 (g=1) own slots 4..6.
// Uniform control flow: 4-slot loops with clamped index + guarded writes.
__global__ __launch_bounds__(128) void kupd(
    const float* __restrict__ Wv, const float* __restrict__ W_ih,
    const float* __restrict__ W_hh, const float* __restrict__ b_ih,
    const float* __restrict__ b_hh, const float* __restrict__ w1,
    const float* __restrict__ b1p, const float* __restrict__ w2,
    const float* __restrict__ b2p, const float* __restrict__ lmg,
    const float* __restrict__ lmb, const float* __restrict__ lsg,
    const float* __restrict__ lsb, float* __restrict__ out, int last) {
    __shared__ __align__(16) float sU[7][64], sPrev[7][64], sUpd[7][64],
                                   sM_[7][64], sHid[7][128];
    __shared__ float s_red[4][4][2], s_rden[7];
    int b = blockIdx.x, tid = threadIdx.x;
    int g = tid >> 6, d = tid & 63;
    int lane = tid & 31, w = tid >> 5;
    int S0 = g * 4, ns = 4 - g;
    int sidx[4];
#pragma unroll
    for (int sl = 0; sl < 4; sl++) sidx[sl] = S0 + (sl < ns ? sl : ns - 1);

    // ---- P0: reduce partials ----
    float num[4];
#pragma unroll
    for (int sl = 0; sl < 4; sl++) num[sl] = 0.f;
    const float* pp = g_part + (size_t)b * NCH * SD + d;
#pragma unroll
    for (int c = 0; c < NCH; c++)
#pragma unroll
        for (int sl = 0; sl < 4; sl++)
            num[sl] += pp[c * SD + sidx[sl] * 64];
    if (d < ns) {
        float dn = 0.f;
        const float* dp = g_pden + b * NCH * 7 + S0 + d;
#pragma unroll
        for (int c = 0; c < NCH; c++) dn += dp[c * 7];
        s_rden[S0 + d] = 1.0f / dn;
    }
    float prev[4];
#pragma unroll
    for (int sl = 0; sl < 4; sl++) {
        prev[sl] = g_slots[b * SD + sidx[sl] * 64 + d];
        if (sl < ns) sPrev[sidx[sl]][d] = prev[sl];
    }
    __syncthreads();
#pragma unroll
    for (int sl = 0; sl < 4; sl++)
        if (sl < ns) sU[sidx[sl]][d] = num[sl] * s_rden[sidx[sl]];
    __syncthreads();

    // ---- P1: upd = U @ Wv^T ----
    ull upd2[4];
#pragma unroll
    for (int sl = 0; sl < 4; sl++) upd2[sl] = 0ull;
    const ulonglong2* wv4 = (const ulonglong2*)(Wv + d * 64);
#pragma unroll
    for (int i = 0; i < 16; i++) {
        ulonglong2 wp = wv4[i];
#pragma unroll
        for (int sl = 0; sl < 4; sl++) {
            ulonglong2 uq = ((const ulonglong2*)sU[sidx[sl]])[i];
            fma2(upd2[sl], wp.x, uq.x); fma2(upd2[sl], wp.y, uq.y);
        }
    }
#pragma unroll
    for (int sl = 0; sl < 4; sl++)
        if (sl < ns) {
            float2 t = up2(upd2[sl]);
            sUpd[sidx[sl]][d] = t.x + t.y;
        }
    __syncthreads();

    // ---- P2: GRU gates ----
    ull g2[6][4];
#pragma unroll
    for (int gg = 0; gg < 6; gg++)
#pragma unroll
        for (int sl = 0; sl < 4; sl++) g2[gg][sl] = 0ull;
    const ulonglong2* wi0 = (const ulonglong2*)(W_ih + d * 64);
    const ulonglong2* wi1 = (const ulonglong2*)(W_ih + (64 + d) * 64);
    const ulonglong2* wi2 = (const ulonglong2*)(W_ih + (128 + d) * 64);
    const ulonglong2* wh0 = (const ulonglong2*)(W_hh + d * 64);
    const ulonglong2* wh1 = (const ulonglong2*)(W_hh + (64 + d) * 64);
    const ulonglong2* wh2 = (const ulonglong2*)(W_hh + (128 + d) * 64);
#pragma unroll
    for (int i = 0; i < 16; i++) {
        ulonglong2 a0 = wi0[i], a1 = wi1[i], a2 = wi2[i];
        ulonglong2 h0 = wh0[i], h1 = wh1[i], h2 = wh2[i];
#pragma unroll
        for (int sl = 0; sl < 4; sl++) {
            ulonglong2 uq = ((const ulonglong2*)sUpd[sidx[sl]])[i];
            ulonglong2 pq = ((const ulonglong2*)sPrev[sidx[sl]])[i];
            fma2(g2[0][sl], a0.x, uq.x); fma2(g2[0][sl], a0.y, uq.y);
            fma2(g2[1][sl], a1.x, uq.x); fma2(g2[1][sl], a1.y, uq.y);
            fma2(g2[2][sl], a2.x, uq.x); fma2(g2[2][sl], a2.y, uq.y);
            fma2(g2[3][sl], h0.x, pq.x); fma2(g2[3][sl], h0.y, pq.y);
            fma2(g2[4][sl], h1.x, pq.x); fma2(g2[4][sl], h1.y, pq.y);
            fma2(g2[5][sl], h2.x, pq.x); fma2(g2[5][sl], h2.y, pq.y);
        }
    }
    float bi0 = b_ih[d], bi1 = b_ih[64 + d], bi2 = b_ih[128 + d];
    float bh0 = b_hh[d], bh1 = b_hh[64 + d], bh2 = b_hh[128 + d];
    float h[4];
#pragma unroll
    for (int sl = 0; sl < 4; sl++) {
        float2 t;
        t = up2(g2[0][sl]); float gi0 = t.x + t.y + bi0;
        t = up2(g2[1][sl]); float gi1 = t.x + t.y + bi1;
        t = up2(g2[2][sl]); float gi2 = t.x + t.y + bi2;
        t = up2(g2[3][sl]); float gh0 = t.x + t.y + bh0;
        t = up2(g2[4][sl]); float gh1 = t.x + t.y + bh1;
        t = up2(g2[5][sl]); float gh2 = t.x + t.y + bh2;
        float r = sigf(gi0 + gh0);
        float z = sigf(gi1 + gh1);
        float n = tanhf(gi2 + r * gh2);
        h[sl] = (1.0f - z) * n + z * prev[sl];
    }

    // ---- P3: LN(h) with ln_mlp ----
#pragma unroll
    for (int sl = 0; sl < 4; sl++) {
        float s1 = h[sl], s2 = h[sl] * h[sl];
#pragma unroll
        for (int off = 16; off; off >>= 1) {
            s1 += __shfl_xor_sync(0xffffffffu, s1, off);
            s2 += __shfl_xor_sync(0xffffffffu, s2, off);
        }
        if (lane == 0) { s_red[w][sl][0] = s1; s_red[w][sl][1] = s2; }
    }
    __syncthreads();
    float lgd = lmg[d], lbd = lmb[d];
#pragma unroll
    for (int sl = 0; sl < 4; sl++) {
        float tot  = s_red[2 * g][sl][0] + s_red[2 * g + 1][sl][0];
        float tot2 = s_red[2 * g][sl][1] + s_red[2 * g + 1][sl][1];
        float mu = tot * (1.0f / 64.0f);
        float rs = rsqrtf(tot2 * (1.0f / 64.0f) - mu * mu + 1e-5f);
        if (sl < ns) sM_[sidx[sl]][d] = fmaf((h[sl] - mu) * rs, lgd, lbd);
    }
    __syncthreads();

    // ---- P4: MLP layer 1 (64 -> 128, relu) ----
    ull ha[4], hb[4];
#pragma unroll
    for (int sl = 0; sl < 4; sl++) { ha[sl] = 0ull; hb[sl] = 0ull; }
    const ulonglong2* w1a = (const ulonglong2*)(w1 + d * 64);
    const ulonglong2* w1b = (const ulonglong2*)(w1 + (64 + d) * 64);
#pragma unroll
    for (int i = 0; i < 16; i++) {
        ulonglong2 aa = w1a[i], bb = w1b[i];
#pragma unroll
        for (int sl = 0; sl < 4; sl++) {
            ulonglong2 m = ((const ulonglong2*)sM_[sidx[sl]])[i];
            fma2(ha[sl], aa.x, m.x); fma2(ha[sl], aa.y, m.y);
            fma2(hb[sl], bb.x, m.x); fma2(hb[sl], bb.y, m.y);
        }
    }
    float b1a = b1p[d], b1b = b1p[64 + d];
#pragma unroll
    for (int sl = 0; sl < 4; sl++)
        if (sl < ns) {
            float2 t = up2(ha[sl]);
            sHid[sidx[sl]][d] = fmaxf(t.x + t.y + b1a, 0.f);
            t = up2(hb[sl]);
            sHid[sidx[sl]][64 + d] = fmaxf(t.x + t.y + b1b, 0.f);
        }
    __syncthreads();

    // ---- P5: MLP layer 2 (128 -> 64) + residual ----
    ull mo2[4];
#pragma unroll
    for (int sl = 0; sl < 4; sl++) mo2[sl] = 0ull;
    const ulonglong2* w2r = (const ulonglong2*)(w2 + d * 128);
#pragma unroll
    for (int i = 0; i < 32; i++) {
        ulonglong2 aa = w2r[i];
#pragma unroll
        for (int sl = 0; sl < 4; sl++) {
            ulonglong2 hh = ((const ulonglong2*)sHid[sidx[sl]])[i];
            fma2(mo2[sl], aa.x, hh.x); fma2(mo2[sl], aa.y, hh.y);
        }
    }
    float bb2 = b2p[d];
    float res[4];
#pragma unroll
    for (int sl = 0; sl < 4; sl++) {
        float2 t = up2(mo2[sl]);
        res[sl] = h[sl] + t.x + t.y + bb2;
        if (sl < ns) {
            g_slots[b * SD + sidx[sl] * 64 + d] = res[sl];
            if (last) out[b * SD + sidx[sl] * 64 + d] = res[sl];
        }
    }
    if (last) return;

    // ---- P6: qk for next iteration: LN(res, ln_slot) @ M ----
#pragma unroll
    for (int sl = 0; sl < 4; sl++) {
        float s1 = res[sl], s2 = res[sl] * res[sl];
#pragma unroll
        for (int off = 16; off; off >>= 1) {
            s1 += __shfl_xor_sync(0xffffffffu, s1, off);
            s2 += __shfl_xor_sync(0xffffffffu, s2, off);
        }
        if (lane == 0) { s_red[w][sl][0] = s1; s_red[w][sl][1] = s2; }
    }
    __syncthreads();
    float sgd = lsg[d], sbd = lsb[d];
#pragma unroll
    for (int sl = 0; sl < 4; sl++) {
        float tot  = s_red[2 * g][sl][0] + s_red[2 * g + 1][sl][0];
        float tot2 = s_red[2 * g][sl][1] + s_red[2 * g + 1][sl][1];
        float mu = tot * (1.0f / 64.0f);
        float rs = rsqrtf(tot2 * (1.0f / 64.0f) - mu * mu + 1e-5f);
        if (sl < ns) sM_[sidx[sl]][d] = fmaf((res[sl] - mu) * rs, sgd, sbd);
    }
    __syncthreads();

    float kacc[4];
#pragma unroll
    for (int sl = 0; sl < 4; sl++) kacc[sl] = 0.f;
#pragma unroll
    for (int i = 0; i < 16; i++) {
        float m0 = g_M[(4 * i + 0) * 64 + d], m1 = g_M[(4 * i + 1) * 64 + d];
        float m2 = g_M[(4 * i + 2) * 64 + d], m3 = g_M[(4 * i + 3) * 64 + d];
#pragma unroll
        for (int sl = 0; sl < 4; sl++) {
            float4 x = ((const float4*)sM_[sidx[sl]])[i];
            kacc[sl] = fmaf(x.x, m0, kacc[sl]); kacc[sl] = fmaf(x.y, m1, kacc[sl]);
            kacc[sl] = fmaf(x.z, m2, kacc[sl]); kacc[sl] = fmaf(x.w, m3, kacc[sl]);
        }
    }
#pragma unroll
    for (int sl = 0; sl < 4; sl++)
        if (sl < ns) g_qk[b * SD + sidx[sl] * 64 + d] = kacc[sl];
}

extern "C" void kernel_launch(void* const* d_in, const int* in_sizes, int n_in,
                              void* d_out, int out_size) {
    const float* inputs = (const float*)d_in[0];
    const float* nbg    = (const float*)d_in[1];
    const float* nfg    = (const float*)d_in[2];
    const float* lin_g  = (const float*)d_in[3];
    const float* lin_b  = (const float*)d_in[4];
    const float* lsl_g  = (const float*)d_in[5];
    const float* lsl_b  = (const float*)d_in[6];
    const float* lml_g  = (const float*)d_in[7];
    const float* lml_b  = (const float*)d_in[8];
    const float* Wq     = (const float*)d_in[9];
    const float* Wk     = (const float*)d_in[10];
    const float* Wv     = (const float*)d_in[11];
    const float* W_ih   = (const float*)d_in[12];
    const float* W_hh   = (const float*)d_in[13];
    const float* b_ih   = (const float*)d_in[14];
    const float* b_hh   = (const float*)d_in[15];
    const float* w1     = (const float*)d_in[16];
    const float* b1     = (const float*)d_in[17];
    const float* w2     = (const float*)d_in[18];
    const float* b2     = (const float*)d_in[19];
    const float* bmu    = (const float*)d_in[20];
    const float* bls    = (const float*)d_in[21];
    const float* fmu    = (const float*)d_in[22];
    const float* fls    = (const float*)d_in[23];
    float* out = (float*)d_out;

    kprep<<<64, 64>>>(Wq, Wk);
    kinitq<<<BB, SD>>>(nbg, nfg, bmu, bls, fmu, fls, lsl_g, lsl_b);
    for (int it = 0; it < 3; it++) {
        dim3 ga(NCH, BB);
        kattn<<<ga, 256>>>(inputs, lin_g, lin_b);
        kupd<<<BB, 128>>>(Wv, W_ih, W_hh, b_ih, b_hh, w1, b1, w2, b2,
                          lml_g, lml_b, lsl_g, lsl_b, out, it == 2);
    }
}

// round 8
// speedup vs baseline: 1.2488x; 1.2488x over previous
#include <cuda_runtime.h>

#define BB 128
#define NN 4096
#define SD 448
#define NCH 4

__device__ float g_slots[BB * SD];
__device__ float g_qk[BB * SD];
__device__ float g_part[BB * NCH * SD];
__device__ float g_pden[BB * NCH * 7];
__device__ float g_M[64 * 64];

typedef unsigned long long ull;

__device__ __forceinline__ void fma2(ull& c, ull a, ull b) {
    asm("fma.rn.f32x2 %0, %1, %2, %0;" : "+l"(c) : "l"(a), "l"(b));
}
__device__ __forceinline__ ull pk2(float x, float y) {
    ull r; asm("mov.b64 %0, {%1, %2};" : "=l"(r) : "f"(x), "f"(y)); return r;
}
__device__ __forceinline__ float2 up2(ull v) {
    float2 r; asm("mov.b64 {%0, %1}, %2;" : "=f"(r.x), "=f"(r.y) : "l"(v)); return r;
}
__device__ __forceinline__ float ex2a(float x) {
    float y; asm("ex2.approx.f32 %0, %1;" : "=f"(y) : "f"(x)); return y;
}
__device__ __forceinline__ float rcpa(float x) {
    float y; asm("rcp.approx.f32 %0, %1;" : "=f"(y) : "f"(x)); return y;
}
__device__ __forceinline__ float sigf(float x) { return 1.0f / (1.0f + __expf(-x)); }

// ================= kprep: M = C * Wq^T @ Wk (once) =================
__global__ void kprep(const float* __restrict__ Wq, const float* __restrict__ Wk) {
    int e = blockIdx.x, d = threadIdx.x;
    float acc = 0.f;
#pragma unroll 16
    for (int j = 0; j < 64; j++)
        acc = fmaf(Wq[j * 64 + e], Wk[j * 64 + d], acc);
    g_M[e * 64 + d] = acc * 0.18033688011112042f;  // D^-0.5 * log2(e)
}

// ====== kinitq: slots init + LN(slots) + qk = sn @ M ======
__global__ __launch_bounds__(448) void kinitq(
    const float* __restrict__ nbg, const float* __restrict__ nfg,
    const float* __restrict__ bmu, const float* __restrict__ bls,
    const float* __restrict__ fmu, const float* __restrict__ fls,
    const float* __restrict__ lg, const float* __restrict__ lb) {
    __shared__ __align__(16) float sn[7][64];
    __shared__ float s_red[14][2];
    int b = blockIdx.x, t = threadIdx.x, s = t >> 6, d = t & 63, w = t >> 5;
    float val;
    if (s == 0) val = bmu[d] + expf(bls[d]) * nbg[b * 64 + d];
    else        val = fmu[d] + expf(fls[d]) * nfg[(b * 6 + (s - 1)) * 64 + d];
    g_slots[b * SD + t] = val;

    float s1 = val, s2 = val * val;
#pragma unroll
    for (int off = 16; off; off >>= 1) {
        s1 += __shfl_xor_sync(0xffffffffu, s1, off);
        s2 += __shfl_xor_sync(0xffffffffu, s2, off);
    }
    if ((t & 31) == 0) { s_red[w][0] = s1; s_red[w][1] = s2; }
    __syncthreads();
    float tot  = s_red[2 * s][0] + s_red[2 * s + 1][0];
    float tot2 = s_red[2 * s][1] + s_red[2 * s + 1][1];
    float mu = tot * (1.0f / 64.0f);
    float rs = rsqrtf(tot2 * (1.0f / 64.0f) - mu * mu + 1e-5f);
    sn[s][d] = fmaf((val - mu) * rs, lg[d], lb[d]);
    __syncthreads();

    float acc = 0.f;
    const float4* sn4 = (const float4*)sn[s];
#pragma unroll
    for (int i = 0; i < 16; i++) {
        float4 x = sn4[i];
        float m0 = g_M[(4 * i + 0) * 64 + d], m1 = g_M[(4 * i + 1) * 64 + d];
        float m2 = g_M[(4 * i + 2) * 64 + d], m3 = g_M[(4 * i + 3) * 64 + d];
        acc = fmaf(x.x, m0, acc); acc = fmaf(x.y, m1, acc);
        acc = fmaf(x.z, m2, acc); acc = fmaf(x.w, m3, acc);
    }
    g_qk[b * SD + t] = acc;
}

// ===== kattn: fused LN(inputs) -> logits -> softmax(+eps) -> U/den partials =====
// NOTE: no min-blocks clause — ~140 regs spill-free is faster than 2 blocks w/ spills.
__global__ __launch_bounds__(256) void kattn(const float* __restrict__ x,
                                             const float* __restrict__ lg,
                                             const float* __restrict__ lb) {
    __shared__ __align__(16) float s_qk[7][64];
    __shared__ float s_u[8][7][64];
    __shared__ float s_d[8][7];
    int b = blockIdx.y, chunk = blockIdx.x;
    int tid = threadIdx.x, warp = tid >> 5, lane = tid & 31;
    int grp = lane >> 3, sub = lane & 7, d0 = sub << 3;

    for (int i = tid; i < SD; i += 256)
        ((float*)s_qk)[i] = g_qk[b * SD + i];

    float lng[8], lnb[8];
#pragma unroll
    for (int j = 0; j < 8; j++) { lng[j] = lg[d0 + j]; lnb[j] = lb[d0 + j]; }

    ull U[7][4];
    float den[7];
#pragma unroll
    for (int s = 0; s < 7; s++) {
        den[s] = 0.f;
#pragma unroll
        for (int j = 0; j < 4; j++) U[s][j] = 0ull;
    }
    __syncthreads();

    const int ROWS = NN / NCH;          // 1024 rows per block
    const int STEPS = ROWS / 32;        // 32 steps per group
    const float* xp = x + ((size_t)b * NN + chunk * ROWS + warp * 4 + grp) * 64 + d0;
    float4 cx0 = *(const float4*)xp;
    float4 cx1 = *(const float4*)(xp + 4);

#pragma unroll 4
    for (int step = 0; step < STEPS; step++) {
        float4 nx0 = cx0, nx1 = cx1;
        if (step < STEPS - 1) {
            xp += 32 * 64;
            nx0 = *(const float4*)xp;
            nx1 = *(const float4*)(xp + 4);
        }
        float s1 = cx0.x + cx0.y + cx0.z + cx0.w + cx1.x + cx1.y + cx1.z + cx1.w;
        float s2 = 0.f;
        s2 = fmaf(cx0.x, cx0.x, s2); s2 = fmaf(cx0.y, cx0.y, s2);
        s2 = fmaf(cx0.z, cx0.z, s2); s2 = fmaf(cx0.w, cx0.w, s2);
        s2 = fmaf(cx1.x, cx1.x, s2); s2 = fmaf(cx1.y, cx1.y, s2);
        s2 = fmaf(cx1.z, cx1.z, s2); s2 = fmaf(cx1.w, cx1.w, s2);
#pragma unroll
        for (int off = 1; off <= 4; off <<= 1) {
            s1 += __shfl_xor_sync(0xffffffffu, s1, off);
            s2 += __shfl_xor_sync(0xffffffffu, s2, off);
        }
        float mu = s1 * (1.0f / 64.0f);
        float rs = rsqrtf(s2 * (1.0f / 64.0f) - mu * mu + 1e-5f);
        ull p[4];
        p[0] = pk2(fmaf((cx0.x - mu) * rs, lng[0], lnb[0]),
                   fmaf((cx0.y - mu) * rs, lng[1], lnb[1]));
        p[1] = pk2(fmaf((cx0.z - mu) * rs, lng[2], lnb[2]),
                   fmaf((cx0.w - mu) * rs, lng[3], lnb[3]));
        p[2] = pk2(fmaf((cx1.x - mu) * rs, lng[4], lnb[4]),
                   fmaf((cx1.y - mu) * rs, lng[5], lnb[5]));
        p[3] = pk2(fmaf((cx1.z - mu) * rs, lng[6], lnb[6]),
                   fmaf((cx1.w - mu) * rs, lng[7], lnb[7]));
        float l[7];
#pragma unroll
        for (int s = 0; s < 7; s++) {
            const ull* qrow = (const ull*)&s_qk[s][d0];
            ull acc = 0ull;
            fma2(acc, p[0], qrow[0]); fma2(acc, p[1], qrow[1]);
            fma2(acc, p[2], qrow[2]); fma2(acc, p[3], qrow[3]);
            float2 pf = up2(acc);
            l[s] = pf.x + pf.y;
        }
#pragma unroll
        for (int off = 1; off <= 4; off <<= 1)
#pragma unroll
            for (int s = 0; s < 7; s++)
                l[s] += __shfl_xor_sync(0xffffffffu, l[s], off);
        // softmax without max-subtraction (|l| small; ratio exactly invariant)
        float ws = 0.f;
#pragma unroll
        for (int s = 0; s < 7; s++) { l[s] = ex2a(l[s]); ws += l[s]; }
        float rinv = rcpa(ws);
#pragma unroll
        for (int s = 0; s < 7; s++) {
            float wv = fmaf(l[s], rinv, 1e-8f);
            den[s] += wv;
            ull wp = pk2(wv, wv);
            fma2(U[s][0], wp, p[0]); fma2(U[s][1], wp, p[1]);
            fma2(U[s][2], wp, p[2]); fma2(U[s][3], wp, p[3]);
        }
        cx0 = nx0; cx1 = nx1;
    }

    float u[7][8];
#pragma unroll
    for (int s = 0; s < 7; s++)
#pragma unroll
        for (int j = 0; j < 4; j++) {
            float2 t2 = up2(U[s][j]);
            u[s][2 * j] = t2.x; u[s][2 * j + 1] = t2.y;
        }
#pragma unroll
    for (int off = 8; off <= 16; off <<= 1) {
#pragma unroll
        for (int s = 0; s < 7; s++) {
#pragma unroll
            for (int j = 0; j < 8; j++)
                u[s][j] += __shfl_xor_sync(0xffffffffu, u[s][j], off);
            den[s] += __shfl_xor_sync(0xffffffffu, den[s], off);
        }
    }
    if (lane < 8) {
#pragma unroll
        for (int s = 0; s < 7; s++)
#pragma unroll
            for (int j = 0; j < 8; j++)
                s_u[warp][s][lane * 8 + j] = u[s][j];
    }
    if (lane == 0)
#pragma unroll
        for (int s = 0; s < 7; s++) s_d[warp][s] = den[s];
    __syncthreads();

    float* outp = g_part + (size_t)(b * NCH + chunk) * SD;
    for (int idx = tid; idx < SD; idx += 256) {
        int s = idx >> 6, d = idx & 63;
        float a = 0.f;
#pragma unroll
        for (int w8 = 0; w8 < 8; w8++) a += s_u[w8][s][d];
        outp[idx] = a;
    }
    if (tid < 7) {
        float a = 0.f;
#pragma unroll
        for (int w8 = 0; w8 < 8; w8++) a += s_d[w8][tid];
        g_pden[(b * NCH + chunk) * 7 + tid] = a;
    }
}

// ===== kupd: partial-reduce -> Wv -> GRU -> LN -> MLP -> (next qk) =====
// block = 128: warps 0-1 (g=0) own slots 0..3; warps 2-3 (g=1) own slots 4..6.
__global__ __launch_bounds__(128) void kupd(
    const float* __restrict__ Wv, const float* __restrict__ W_ih,
    const float* __restrict__ W_hh, const float* __restrict__ b_ih,
    const float* __restrict__ b_hh, const float* __restrict__ w1,
    const float* __restrict__ b1p, const float* __restrict__ w2,
    const float* __restrict__ b2p, const float* __restrict__ lmg,
    const float* __restrict__ lmb, const float* __restrict__ lsg,
    const float* __restrict__ lsb, float* __restrict__ out, int last) {
    __shared__ __align__(16) float sU[7][64], sPrev[7][64], sUpd[7][64],
                                   sM_[7][64], sHid[7][128];
    __shared__ float s_red[4][4][2], s_rden[7];
    int b = blockIdx.x, tid = threadIdx.x;
    int g = tid >> 6, d = tid & 63;
    int lane = tid & 31, w = tid >> 5;
    int S0 = g * 4, ns = 4 - g;
    int sidx[4];
#pragma unroll
    for (int sl = 0; sl < 4; sl++) sidx[sl] = S0 + (sl < ns ? sl : ns - 1);

    // ---- P0: reduce partials ----
    float num[4];
#pragma unroll
    for (int sl = 0; sl < 4; sl++) num[sl] = 0.f;
    const float* pp = g_part + (size_t)b * NCH * SD + d;
#pragma unroll
    for (int c = 0; c < NCH; c++)
#pragma unroll
        for (int sl = 0; sl < 4; sl++)
            num[sl] += pp[c * SD + sidx[sl] * 64];
    if (d < ns) {
        float dn = 0.f;
        const float* dp = g_pden + b * NCH * 7 + S0 + d;
#pragma unroll
        for (int c = 0; c < NCH; c++) dn += dp[c * 7];
        s_rden[S0 + d] = 1.0f / dn;
    }
    float prev[4];
#pragma unroll
    for (int sl = 0; sl < 4; sl++) {
        prev[sl] = g_slots[b * SD + sidx[sl] * 64 + d];
        if (sl < ns) sPrev[sidx[sl]][d] = prev[sl];
    }
    __syncthreads();
#pragma unroll
    for (int sl = 0; sl < 4; sl++)
        if (sl < ns) sU[sidx[sl]][d] = num[sl] * s_rden[sidx[sl]];
    __syncthreads();

    // ---- P1: upd = U @ Wv^T ----
    ull upd2[4];
#pragma unroll
    for (int sl = 0; sl < 4; sl++) upd2[sl] = 0ull;
    const ulonglong2* wv4 = (const ulonglong2*)(Wv + d * 64);
#pragma unroll
    for (int i = 0; i < 16; i++) {
        ulonglong2 wp = wv4[i];
#pragma unroll
        for (int sl = 0; sl < 4; sl++) {
            ulonglong2 uq = ((const ulonglong2*)sU[sidx[sl]])[i];
            fma2(upd2[sl], wp.x, uq.x); fma2(upd2[sl], wp.y, uq.y);
        }
    }
#pragma unroll
    for (int sl = 0; sl < 4; sl++)
        if (sl < ns) {
            float2 t = up2(upd2[sl]);
            sUpd[sidx[sl]][d] = t.x + t.y;
        }
    __syncthreads();

    // ---- P2: GRU gates ----
    ull g2[6][4];
#pragma unroll
    for (int gg = 0; gg < 6; gg++)
#pragma unroll
        for (int sl = 0; sl < 4; sl++) g2[gg][sl] = 0ull;
    const ulonglong2* wi0 = (const ulonglong2*)(W_ih + d * 64);
    const ulonglong2* wi1 = (const ulonglong2*)(W_ih + (64 + d) * 64);
    const ulonglong2* wi2 = (const ulonglong2*)(W_ih + (128 + d) * 64);
    const ulonglong2* wh0 = (const ulonglong2*)(W_hh + d * 64);
    const ulonglong2* wh1 = (const ulonglong2*)(W_hh + (64 + d) * 64);
    const ulonglong2* wh2 = (const ulonglong2*)(W_hh + (128 + d) * 64);
#pragma unroll
    for (int i = 0; i < 16; i++) {
        ulonglong2 a0 = wi0[i], a1 = wi1[i], a2 = wi2[i];
        ulonglong2 h0 = wh0[i], h1 = wh1[i], h2 = wh2[i];
#pragma unroll
        for (int sl = 0; sl < 4; sl++) {
            ulonglong2 uq = ((const ulonglong2*)sUpd[sidx[sl]])[i];
            ulonglong2 pq = ((const ulonglong2*)sPrev[sidx[sl]])[i];
            fma2(g2[0][sl], a0.x, uq.x); fma2(g2[0][sl], a0.y, uq.y);
            fma2(g2[1][sl], a1.x, uq.x); fma2(g2[1][sl], a1.y, uq.y);
            fma2(g2[2][sl], a2.x, uq.x); fma2(g2[2][sl], a2.y, uq.y);
            fma2(g2[3][sl], h0.x, pq.x); fma2(g2[3][sl], h0.y, pq.y);
            fma2(g2[4][sl], h1.x, pq.x); fma2(g2[4][sl], h1.y, pq.y);
            fma2(g2[5][sl], h2.x, pq.x); fma2(g2[5][sl], h2.y, pq.y);
        }
    }
    float bi0 = b_ih[d], bi1 = b_ih[64 + d], bi2 = b_ih[128 + d];
    float bh0 = b_hh[d], bh1 = b_hh[64 + d], bh2 = b_hh[128 + d];
    float h[4];
#pragma unroll
    for (int sl = 0; sl < 4; sl++) {
        float2 t;
        t = up2(g2[0][sl]); float gi0 = t.x + t.y + bi0;
        t = up2(g2[1][sl]); float gi1 = t.x + t.y + bi1;
        t = up2(g2[2][sl]); float gi2 = t.x + t.y + bi2;
        t = up2(g2[3][sl]); float gh0 = t.x + t.y + bh0;
        t = up2(g2[4][sl]); float gh1 = t.x + t.y + bh1;
        t = up2(g2[5][sl]); float gh2 = t.x + t.y + bh2;
        float r = sigf(gi0 + gh0);
        float z = sigf(gi1 + gh1);
        float n = tanhf(gi2 + r * gh2);
        h[sl] = (1.0f - z) * n + z * prev[sl];
    }

    // ---- P3: LN(h) with ln_mlp ----
#pragma unroll
    for (int sl = 0; sl < 4; sl++) {
        float s1 = h[sl], s2 = h[sl] * h[sl];
#pragma unroll
        for (int off = 16; off; off >>= 1) {
            s1 += __shfl_xor_sync(0xffffffffu, s1, off);
            s2 += __shfl_xor_sync(0xffffffffu, s2, off);
        }
        if (lane == 0) { s_red[w][sl][0] = s1; s_red[w][sl][1] = s2; }
    }
    __syncthreads();
    float lgd = lmg[d], lbd = lmb[d];
#pragma unroll
    for (int sl = 0; sl < 4; sl++) {
        float tot  = s_red[2 * g][sl][0] + s_red[2 * g + 1][sl][0];
        float tot2 = s_red[2 * g][sl][1] + s_red[2 * g + 1][sl][1];
        float mu = tot * (1.0f / 64.0f);
        float rs = rsqrtf(tot2 * (1.0f / 64.0f) - mu * mu + 1e-5f);
        if (sl < ns) sM_[sidx[sl]][d] = fmaf((h[sl] - mu) * rs, lgd, lbd);
    }
    __syncthreads();

    // ---- P4: MLP layer 1 (64 -> 128, relu) ----
    ull ha[4], hb[4];
#pragma unroll
    for (int sl = 0; sl < 4; sl++) { ha[sl] = 0ull; hb[sl] = 0ull; }
    const ulonglong2* w1a = (const ulonglong2*)(w1 + d * 64);
    const ulonglong2* w1b = (const ulonglong2*)(w1 + (64 + d) * 64);
#pragma unroll
    for (int i = 0; i < 16; i++) {
        ulonglong2 aa = w1a[i], bb = w1b[i];
#pragma unroll
        for (int sl = 0; sl < 4; sl++) {
            ulonglong2 m = ((const ulonglong2*)sM_[sidx[sl]])[i];
            fma2(ha[sl], aa.x, m.x); fma2(ha[sl], aa.y, m.y);
            fma2(hb[sl], bb.x, m.x); fma2(hb[sl], bb.y, m.y);
        }
    }
    float b1a = b1p[d], b1b = b1p[64 + d];
#pragma unroll
    for (int sl = 0; sl < 4; sl++)
        if (sl < ns) {
            float2 t = up2(ha[sl]);
            sHid[sidx[sl]][d] = fmaxf(t.x + t.y + b1a, 0.f);
            t = up2(hb[sl]);
            sHid[sidx[sl]][64 + d] = fmaxf(t.x + t.y + b1b, 0.f);
        }
    __syncthreads();

    // ---- P5: MLP layer 2 (128 -> 64) + residual ----
    ull mo2[4];
#pragma unroll
    for (int sl = 0; sl < 4; sl++) mo2[sl] = 0ull;
    const ulonglong2* w2r = (const ulonglong2*)(w2 + d * 128);
#pragma unroll
    for (int i = 0; i < 32; i++) {
        ulonglong2 aa = w2r[i];
#pragma unroll
        for (int sl = 0; sl < 4; sl++) {
            ulonglong2 hh = ((const ulonglong2*)sHid[sidx[sl]])[i];
            fma2(mo2[sl], aa.x, hh.x); fma2(mo2[sl], aa.y, hh.y);
        }
    }
    float bb2 = b2p[d];
    float res[4];
#pragma unroll
    for (int sl = 0; sl < 4; sl++) {
        float2 t = up2(mo2[sl]);
        res[sl] = h[sl] + t.x + t.y + bb2;
        if (sl < ns) {
            g_slots[b * SD + sidx[sl] * 64 + d] = res[sl];
            if (last) out[b * SD + sidx[sl] * 64 + d] = res[sl];
        }
    }
    if (last) return;

    // ---- P6: qk for next iteration: LN(res, ln_slot) @ M ----
#pragma unroll
    for (int sl = 0; sl < 4; sl++) {
        float s1 = res[sl], s2 = res[sl] * res[sl];
#pragma unroll
        for (int off = 16; off; off >>= 1) {
            s1 += __shfl_xor_sync(0xffffffffu, s1, off);
            s2 += __shfl_xor_sync(0xffffffffu, s2, off);
        }
        if (lane == 0) { s_red[w][sl][0] = s1; s_red[w][sl][1] = s2; }
    }
    __syncthreads();
    float sgd = lsg[d], sbd = lsb[d];
#pragma unroll
    for (int sl = 0; sl < 4; sl++) {
        float tot  = s_red[2 * g][sl][0] + s_red[2 * g + 1][sl][0];
        float tot2 = s_red[2 * g][sl][1] + s_red[2 * g + 1][sl][1];
        float mu = tot * (1.0f / 64.0f);
        float rs = rsqrtf(tot2 * (1.0f / 64.0f) - mu * mu + 1e-5f);
        if (sl < ns) sM_[sidx[sl]][d] = fmaf((res[sl] - mu) * rs, sgd, sbd);
    }
    __syncthreads();

    float kacc[4];
#pragma unroll
    for (int sl = 0; sl < 4; sl++) kacc[sl] = 0.f;
#pragma unroll
    for (int i = 0; i < 16; i++) {
        float m0 = g_M[(4 * i + 0) * 64 + d], m1 = g_M[(4 * i + 1) * 64 + d];
        float m2 = g_M[(4 * i + 2) * 64 + d], m3 = g_M[(4 * i + 3) * 64 + d];
#pragma unroll
        for (int sl = 0; sl < 4; sl++) {
            float4 x = ((const float4*)sM_[sidx[sl]])[i];
            kacc[sl] = fmaf(x.x, m0, kacc[sl]); kacc[sl] = fmaf(x.y, m1, kacc[sl]);
            kacc[sl] = fmaf(x.z, m2, kacc[sl]); kacc[sl] = fmaf(x.w, m3, kacc[sl]);
        }
    }
#pragma unroll
    for (int sl = 0; sl < 4; sl++)
        if (sl < ns) g_qk[b * SD + sidx[sl] * 64 + d] = kacc[sl];
}

extern "C" void kernel_launch(void* const* d_in, const int* in_sizes, int n_in,
                              void* d_out, int out_size) {
    const float* inputs = (const float*)d_in[0];
    const float* nbg    = (const float*)d_in[1];
    const float* nfg    = (const float*)d_in[2];
    const float* lin_g  = (const float*)d_in[3];
    const float* lin_b  = (const float*)d_in[4];
    const float* lsl_g  = (const float*)d_in[5];
    const float* lsl_b  = (const float*)d_in[6];
    const float* lml_g  = (const float*)d_in[7];
    const float* lml_b  = (const float*)d_in[8];
    const float* Wq     = (const float*)d_in[9];
    const float* Wk     = (const float*)d_in[10];
    const float* Wv     = (const float*)d_in[11];
    const float* W_ih   = (const float*)d_in[12];
    const float* W_hh   = (const float*)d_in[13];
    const float* b_ih   = (const float*)d_in[14];
    const float* b_hh   = (const float*)d_in[15];
    const float* w1     = (const float*)d_in[16];
    const float* b1     = (const float*)d_in[17];
    const float* w2     = (const float*)d_in[18];
    const float* b2     = (const float*)d_in[19];
    const float* bmu    = (const float*)d_in[20];
    const float* bls    = (const float*)d_in[21];
    const float* fmu    = (const float*)d_in[22];
    const float* fls    = (const float*)d_in[23];
    float* out = (float*)d_out;

    kprep<<<64, 64>>>(Wq, Wk);
    kinitq<<<BB, SD>>>(nbg, nfg, bmu, bls, fmu, fls, lsl_g, lsl_b);
    for (int it = 0; it < 3; it++) {
        dim3 ga(NCH, BB);
        kattn<<<ga, 256>>>(inputs, lin_g, lin_b);
        kupd<<<BB, 128>>>(Wv, W_ih, W_hh, b_ih, b_hh, w1, b1, w2, b2,
                          lml_g, lml_b, lsl_g, lsl_b, out, it == 2);
    }
}